// round 2
// baseline (speedup 1.0000x reference)
#include <cuda_runtime.h>

// Problem constants (GRUmodule_57105885167750)
#define B_ 2048
#define T_ 512
#define I_ 64
#define H_ 3
#define G_ 9     // 3*H gates
#define PAD_ 12  // padded gate row for float4 alignment

// Scratch: xW0 pre-activations, layout [t][b][12] -> 48 MB (fits mostly in L2)
__device__ float g_xw[(size_t)T_ * B_ * PAD_];

// ---------------------------------------------------------------------------
// Kernel A: xW0[b,t,:] = b_ih0 + x[b,t,:] @ W_ih0^T
// Block = 128 threads = 128 consecutive rows m = b*T + t.
// x staged through smem (coalesced global float4, conflict-free padded rows).
// ---------------------------------------------------------------------------
__global__ __launch_bounds__(128) void xw_gemm_kernel(
    const float* __restrict__ x,
    const float* __restrict__ Wih0,
    const float* __restrict__ bih0)
{
    __shared__ float xs[128 * 68];   // 128 rows, stride 68 (conflict-free LDS.128)
    __shared__ float ws[G_ * I_];    // 9 x 64 weights
    __shared__ float bs[G_];

    const int tid = threadIdx.x;
    const size_t row0 = (size_t)blockIdx.x * 128;

    // stage weights + bias
    for (int i = tid; i < G_ * I_; i += 128) ws[i] = Wih0[i];
    if (tid < G_) bs[tid] = bih0[tid];

    // stage x: 128 rows * 16 float4 = 2048 float4, fully coalesced
    const float4* xg = (const float4*)(x + row0 * I_);
#pragma unroll
    for (int i = 0; i < 16; i++) {
        int idx = i * 128 + tid;           // float4 index in tile
        float4 v = xg[idx];
        int r = idx >> 4;                  // row (16 float4 per row)
        int c = (idx & 15) << 2;           // float column
        *(float4*)&xs[r * 68 + c] = v;
    }
    __syncthreads();

    float acc[9];
#pragma unroll
    for (int j = 0; j < 9; j++) acc[j] = bs[j];

#pragma unroll
    for (int u = 0; u < 16; u++) {
        float4 xv = *(const float4*)&xs[tid * 68 + u * 4];
#pragma unroll
        for (int j = 0; j < 9; j++) {
            float4 wv = *(const float4*)&ws[j * 64 + u * 4];   // broadcast
            acc[j] = fmaf(xv.x, wv.x, acc[j]);
            acc[j] = fmaf(xv.y, wv.y, acc[j]);
            acc[j] = fmaf(xv.z, wv.z, acc[j]);
            acc[j] = fmaf(xv.w, wv.w, acc[j]);
        }
    }

    const size_t m = row0 + tid;
    const int b = (int)(m >> 9);           // T = 512
    const int t = (int)(m & 511);
    float* o = g_xw + ((size_t)t * B_ + b) * PAD_;
    *(float4*)(o)     = make_float4(acc[0], acc[1], acc[2], acc[3]);
    *(float4*)(o + 4) = make_float4(acc[4], acc[5], acc[6], acc[7]);
    *(float4*)(o + 8) = make_float4(acc[8], 0.f, 0.f, 0.f);
}

// ---------------------------------------------------------------------------
// Kernel B: fused two-layer GRU scan.
// Warp of 32 lanes: lanes 0..15 run layer 0 for batches b0..b0+15,
// lanes 16..31 run layer 1 for the SAME batches one timestep behind.
// Uniform instruction stream: layer-0 lanes carry W_ih == 0 so both halves
// execute identical code; h0 handed to layer-1 lanes via shfl (off critical
// path thanks to the 1-step pipeline skew).
// ---------------------------------------------------------------------------
__device__ __forceinline__ float fsig(float x) {
    // overflow-safe: x -> -inf gives exp->inf, 1/inf = 0; x -> +inf gives 1.
    return __fdividef(1.0f, 1.0f + __expf(-x));
}

__global__ __launch_bounds__(32) void gru_scan_kernel(
    const float* __restrict__ Whh0g, const float* __restrict__ bhh0g,
    const float* __restrict__ Wih1g, const float* __restrict__ Whh1g,
    const float* __restrict__ bih1g, const float* __restrict__ bhh1g,
    float* __restrict__ out)
{
    const int lane = threadIdx.x;
    const bool is0 = (lane < 16);
    const int b = blockIdx.x * 16 + (lane & 15);

    // per-lane weights (registers)
    float Wih[9][3], Whh[9][3], bhh[9], bih[9];
#pragma unroll
    for (int j = 0; j < 9; j++) {
#pragma unroll
        for (int k = 0; k < 3; k++) {
            Wih[j][k] = is0 ? 0.0f : Wih1g[j * 3 + k];
            Whh[j][k] = is0 ? Whh0g[j * 3 + k] : Whh1g[j * 3 + k];
        }
        bhh[j] = is0 ? bhh0g[j] : bhh1g[j];
        bih[j] = is0 ? 0.0f : bih1g[j];
    }

    float h0 = 0.f, h1 = 0.f, h2 = 0.f;   // this lane's hidden state
    float p0 = 0.f, p1 = 0.f, p2 = 0.f;   // previous-layer h (layer-1 lanes)

    const float4* base = (const float4*)g_xw;   // float4 index = (t*B + b)*3

    // depth-4 register prefetch pipeline for the per-step 48B xW read
    float4 buf[4][3];
#pragma unroll
    for (int d = 0; d < 3; d++) {
        size_t off = ((size_t)d * B_ + b) * 3;
        buf[d][0] = base[off];
        buf[d][1] = base[off + 1];
        buf[d][2] = base[off + 2];
    }

    // iterations 0..515 (unroll-friendly multiple of 4); layer0 active it<512
    // (timestep = it), layer1 active 1<=it<=512 (timestep = it-1).
#pragma unroll 4
    for (int it = 0; it < 516; it++) {
        // issue prefetch for it+3 (clamped)
        int tf = it + 3; if (tf > T_ - 1) tf = T_ - 1;
        {
            size_t off = ((size_t)tf * B_ + b) * 3;
            buf[(it + 3) & 3][0] = base[off];
            buf[(it + 3) & 3][1] = base[off + 1];
            buf[(it + 3) & 3][2] = base[off + 2];
        }
        const float4 a0 = buf[it & 3][0];
        const float4 a1 = buf[it & 3][1];
        const float4 a2 = buf[it & 3][2];

        float bse[9];
        bse[0] = is0 ? a0.x : bih[0];
        bse[1] = is0 ? a0.y : bih[1];
        bse[2] = is0 ? a0.z : bih[2];
        bse[3] = is0 ? a0.w : bih[3];
        bse[4] = is0 ? a1.x : bih[4];
        bse[5] = is0 ? a1.y : bih[5];
        bse[6] = is0 ? a1.z : bih[6];
        bse[7] = is0 ? a1.w : bih[7];
        bse[8] = is0 ? a2.x : bih[8];

        float xg[9], gh[9];
#pragma unroll
        for (int j = 0; j < 9; j++) {
            xg[j] = fmaf(p2, Wih[j][2], fmaf(p1, Wih[j][1], fmaf(p0, Wih[j][0], bse[j])));
            gh[j] = fmaf(h2, Whh[j][2], fmaf(h1, Whh[j][1], fmaf(h0, Whh[j][0], bhh[j])));
        }

        const float r0 = fsig(xg[0] + gh[0]);
        const float r1 = fsig(xg[1] + gh[1]);
        const float r2 = fsig(xg[2] + gh[2]);
        const float z0 = fsig(xg[3] + gh[3]);
        const float z1 = fsig(xg[4] + gh[4]);
        const float z2 = fsig(xg[5] + gh[5]);
        // tanh(a) = 2*sigmoid(2a) - 1 (overflow-safe)
        float na0 = fmaf(r0, gh[6], xg[6]);
        float na1 = fmaf(r1, gh[7], xg[7]);
        float na2 = fmaf(r2, gh[8], xg[8]);
        const float n0 = fmaf(2.0f, fsig(na0 + na0), -1.0f);
        const float n1 = fmaf(2.0f, fsig(na1 + na1), -1.0f);
        const float n2 = fmaf(2.0f, fsig(na2 + na2), -1.0f);

        const float nh0 = fmaf(z0, h0 - n0, n0);
        const float nh1 = fmaf(z1, h1 - n1, n1);
        const float nh2 = fmaf(z2, h2 - n2, n2);

        const bool active = is0 ? (it < 512) : (it >= 1 && it <= 512);
        h0 = active ? nh0 : h0;
        h1 = active ? nh1 : h1;
        h2 = active ? nh2 : h2;

        // hand layer-0 h to layer-1 partner lane (own value for layer-0 lanes)
        p0 = __shfl_sync(0xffffffffu, h0, lane & 15);
        p1 = __shfl_sync(0xffffffffu, h1, lane & 15);
        p2 = __shfl_sync(0xffffffffu, h2, lane & 15);
    }

    if (!is0) {
        float* o = out + (size_t)b * 3;
        o[0] = h0; o[1] = h1; o[2] = h2;
    }
}

// ---------------------------------------------------------------------------
// Launch
// d_in: 0=x 1=W_ih0 2=W_hh0 3=b_ih0 4=b_hh0 5=W_ih1 6=W_hh1 7=b_ih1 8=b_hh1
// ---------------------------------------------------------------------------
extern "C" void kernel_launch(void* const* d_in, const int* in_sizes, int n_in,
                              void* d_out, int out_size)
{
    const float* x     = (const float*)d_in[0];
    const float* Wih0  = (const float*)d_in[1];
    const float* Whh0  = (const float*)d_in[2];
    const float* bih0  = (const float*)d_in[3];
    const float* bhh0  = (const float*)d_in[4];
    const float* Wih1  = (const float*)d_in[5];
    const float* Whh1  = (const float*)d_in[6];
    const float* bih1  = (const float*)d_in[7];
    const float* bhh1  = (const float*)d_in[8];
    float* out = (float*)d_out;

    // Kernel A: 1,048,576 rows / 128 per block
    xw_gemm_kernel<<<(B_ * T_) / 128, 128>>>(x, Wih0, bih0);

    // Kernel B: 2048 batches, 16 per warp-pair-block
    gru_scan_kernel<<<B_ / 16, 32>>>(Whh0, bhh0, Wih1, Whh1, bih1, bhh1, out);
}